// round 4
// baseline (speedup 1.0000x reference)
#include <cuda_runtime.h>

// Problem-instance capacities (N_KNOTS=2048, DIM=512). Scratch is a __device__
// global (allowed; no runtime allocation).
#define NK_CAP 2048
#define DIM_CAP 512

__device__ float g_cT[(size_t)NK_CAP * DIM_CAP];  // c transposed: [NK][DIM], 4 MB

// ---------------------------------------------------------------------------
// Kernel 1: transpose c[DIM][NK] -> g_cT[NK][DIM] (tiled, conflict-free)
// ---------------------------------------------------------------------------
__global__ void bspline_transpose(const float* __restrict__ c, int DIM, int NK) {
    __shared__ float tile[32][33];
    const int x  = blockIdx.x * 32 + threadIdx.x;  // knot index (c column)
    const int y0 = blockIdx.y * 32;                // dim base   (c row)
    #pragma unroll
    for (int i = threadIdx.y; i < 32; i += 8) {
        int y = y0 + i;
        if (x < NK && y < DIM)
            tile[i][threadIdx.x] = c[(size_t)y * NK + x];
    }
    __syncthreads();
    const int xd  = y0 + threadIdx.x;              // dim index (cT column)
    const int yk0 = blockIdx.x * 32;               // knot base (cT row)
    #pragma unroll
    for (int i = threadIdx.y; i < 32; i += 8) {
        int yk = yk0 + i;
        if (xd < DIM && yk < NK)
            g_cT[(size_t)yk * DIM + xd] = tile[threadIdx.x][i];
    }
}

// ---------------------------------------------------------------------------
// Kernel 2: per-sample span + 4 Cox-de Boor weights, then coalesced 4-row
// weighted sum over cT.
//
// Faithful to the reference's truncated in-place recursion:
//   final row F[i] = B3[i] (i < NK-3), B2[NK-3], B1[NK-2], B0[NK-1].
// Samples with span index beyond NK-1 (s >= t[NK-4]) produce all-zero rows.
// denom==0 -> weight 0, exactly as the reference.
// ---------------------------------------------------------------------------
#define SPB 16   // samples per block
#define TPB 128  // threads per block (DIM/4 = 128 float4 lanes)

__global__ __launch_bounds__(TPB)
void bspline_main(const float* __restrict__ t,
                  const int*   __restrict__ delta_raw,
                  float* __restrict__ out,
                  int NK, int DIM, int S, int sp_count /* 0 or S */) {
    __shared__ float sh_w[SPB][4];
    __shared__ int   sh_c0[SPB];

    const int tid   = threadIdx.x;
    const int sBase = blockIdx.x * SPB;

    // ---- Phase 1: lead threads compute span + weights per sample ----
    if (tid < SPB) {
        // delta arrives as int32 (python int); tolerate float32 encoding too.
        int iv = *delta_raw;
        float delta = (iv > 0 && iv < (1 << 20)) ? (float)iv : __int_as_float(iv);

        const int sidx = sBase + tid;
        float w0 = 0.f, w1 = 0.f, w2 = 0.f, w3 = 0.f;
        int c0 = 0;
        if (sidx < S) {
            const float s = (float)sidx * delta;
            if (sp_count) out[sidx] = s;  // sample_points region

            // ub = first index with t[ub] > s  (span j = ub + 3 in padded knots)
            int lo = 0, hi = NK;
            while (lo < hi) {
                int mid = (lo + hi) >> 1;
                if (__ldg(&t[mid]) > s) hi = mid; else lo = mid + 1;
            }
            const int ub = lo;
            if (ub <= NK - 4) {
                const int j = ub + 3;  // padded-knot span: k[j] <= s < k[j+1]
                // k[m] = K(j-3+m), K(i) = (i<4) ? 0 : t[i-4]; only offsets -2..+3 used
                float k[8];
                #pragma unroll
                for (int m = 1; m <= 6; m++) {
                    int gi = j - 3 + m;
                    k[m] = (gi < 4) ? 0.0f : __ldg(&t[gi - 4]);
                }
                // K(j+off) == k[off+3]
                const float Km2 = k[1], Km1 = k[2], K0 = k[3];
                const float K1  = k[4], K2  = k[5], K3 = k[6];

                auto rat = [](float num, float den) -> float {
                    return (den == 0.0f) ? 0.0f : num / den;
                };

                // degree 1  (B1[j-1], B1[j])
                const float b1a = rat(K1 - s, K1 - K0);
                const float b1b = rat(s - K0, K1 - K0);
                // degree 2  (B2[j-2..j])
                const float b2a = rat(K1 - s, K1 - Km1) * b1a;
                const float b2b = rat(s - Km1, K1 - Km1) * b1a
                                + rat(K2 - s, K2 - K0)   * b1b;
                const float b2c = rat(s - K0, K2 - K0)   * b1b;
                // degree 3  (B3[j-3..j])
                const float b3a = rat(K1 - s, K1 - Km2) * b2a;
                const float b3b = rat(s - Km2, K1 - Km2) * b2a
                                + rat(K2 - s, K2 - Km1)  * b2b;
                const float b3c = rat(s - Km1, K2 - Km1) * b2b
                                + rat(K3 - s, K3 - K0)   * b2c;
                const float b3d = rat(s - K0, K3 - K0)   * b2c;

                const float b3v[4] = {b3a, b3b, b3c, b3d};
                const float b2v[3] = {b2a, b2b, b2c};
                const float b1v[2] = {b1a, b1b};
                float wv[4];
                #pragma unroll
                for (int m = 0; m < 4; m++) {
                    const int col = j - 3 + m;
                    float f = b3v[m];                       // proper deg-3 (col < NK-3)
                    if (col == NK - 3)      f = b2v[m > 0 ? m - 1 : 0];  // stale deg-2
                    else if (col == NK - 2) f = b1v[m > 1 ? m - 2 : 0];  // stale deg-1
                    else if (col == NK - 1) f = 1.0f;                    // stale deg-0
                    wv[m] = f;
                }
                w0 = wv[0]; w1 = wv[1]; w2 = wv[2]; w3 = wv[3];
                c0 = j - 3;
            }
            // else: all-zero row (weights stay 0, c0=0 is a safe read base)
        }
        sh_w[tid][0] = w0; sh_w[tid][1] = w1;
        sh_w[tid][2] = w2; sh_w[tid][3] = w3;
        sh_c0[tid] = c0;
    }
    __syncthreads();

    // ---- Phase 2: weighted 4-row sum, coalesced float4 streams ----
    float* __restrict__ sp = out + sp_count;  // spline_values region
    const bool vec4 = ((DIM & 3) == 0) && ((sp_count & 3) == 0);
    if (vec4) {
        const int DIM4 = DIM >> 2;
        const float4* __restrict__ cT4 = reinterpret_cast<const float4*>(g_cT);
        float4* __restrict__ sp4 = reinterpret_cast<float4*>(sp);
        #pragma unroll 1
        for (int sm = 0; sm < SPB; sm++) {
            const int sidx = sBase + sm;
            if (sidx >= S) break;
            const int   c0 = sh_c0[sm];
            const float w0 = sh_w[sm][0], w1 = sh_w[sm][1];
            const float w2 = sh_w[sm][2], w3 = sh_w[sm][3];
            const float4* r0 = cT4 + (size_t)(c0 + 0) * DIM4;
            const float4* r1 = cT4 + (size_t)(c0 + 1) * DIM4;
            const float4* r2 = cT4 + (size_t)(c0 + 2) * DIM4;
            const float4* r3 = cT4 + (size_t)(c0 + 3) * DIM4;
            float4* o = sp4 + (size_t)sidx * DIM4;
            for (int d = tid; d < DIM4; d += TPB) {
                const float4 v0 = r0[d], v1 = r1[d], v2 = r2[d], v3 = r3[d];
                float4 r;
                r.x = w0 * v0.x + w1 * v1.x + w2 * v2.x + w3 * v3.x;
                r.y = w0 * v0.y + w1 * v1.y + w2 * v2.y + w3 * v3.y;
                r.z = w0 * v0.z + w1 * v1.z + w2 * v2.z + w3 * v3.z;
                r.w = w0 * v0.w + w1 * v1.w + w2 * v2.w + w3 * v3.w;
                o[d] = r;
            }
        }
    } else {
        // scalar fallback (unused for this instance, kept for shape safety)
        #pragma unroll 1
        for (int sm = 0; sm < SPB; sm++) {
            const int sidx = sBase + sm;
            if (sidx >= S) break;
            const int   c0 = sh_c0[sm];
            const float w0 = sh_w[sm][0], w1 = sh_w[sm][1];
            const float w2 = sh_w[sm][2], w3 = sh_w[sm][3];
            for (int d = tid; d < DIM; d += TPB) {
                float r = w0 * g_cT[(size_t)(c0 + 0) * DIM + d]
                        + w1 * g_cT[(size_t)(c0 + 1) * DIM + d]
                        + w2 * g_cT[(size_t)(c0 + 2) * DIM + d]
                        + w3 * g_cT[(size_t)(c0 + 3) * DIM + d];
                sp[(size_t)sidx * DIM + d] = r;
            }
        }
    }
}

// ---------------------------------------------------------------------------
extern "C" void kernel_launch(void* const* d_in, const int* in_sizes, int n_in,
                              void* d_out, int out_size) {
    const float* t     = (const float*)d_in[0];
    const float* c     = (const float*)d_in[1];
    const int*   delta = (const int*)d_in[2];
    float*       out   = (float*)d_out;

    const int NK  = in_sizes[0];                 // 2048
    const int DIM = in_sizes[1] / NK;            // 512

    // Output = concat(sample_points[S], spline[S, DIM]) -> out_size = S*(DIM+1).
    // Fallback: if not divisible, assume spline-only output.
    int S, sp_count;
    if (out_size % (DIM + 1) == 0) { S = out_size / (DIM + 1); sp_count = S; }
    else                           { S = out_size / DIM;       sp_count = 0; }

    // Kernel 1: transpose c into knot-major scratch
    dim3 tb(32, 8);
    dim3 tg((NK + 31) / 32, (DIM + 31) / 32);
    bspline_transpose<<<tg, tb>>>(c, DIM, NK);

    // Kernel 2: spans + weights + streamed weighted sum
    const int grid = (S + SPB - 1) / SPB;
    bspline_main<<<grid, TPB>>>(t, delta, out, NK, DIM, S, sp_count);
}